// round 1
// baseline (speedup 1.0000x reference)
#include <cuda_runtime.h>

#define N_NODES 8192
#define FIN 512
#define FOUT 256
#define ALPHA 0.2f

// Scratch (no cudaMalloc allowed)
__device__ float g_Wh[N_NODES * FOUT];   // 8 MB
__device__ float g_f1[N_NODES];
__device__ float g_f2[N_NODES];
__device__ float g_gmax;

typedef unsigned long long u64;

__device__ __forceinline__ u64 pack2(float lo, float hi) {
    u64 r; asm("mov.b64 %0, {%1, %2};" : "=l"(r) : "f"(lo), "f"(hi)); return r;
}
__device__ __forceinline__ void unpack2(u64 v, float& lo, float& hi) {
    asm("mov.b64 {%0, %1}, %2;" : "=f"(lo), "=f"(hi) : "l"(v));
}
// packed dual fp32 FMA: d = a*b + d  (ptxas never auto-emits FFMA2 from C++)
__device__ __forceinline__ void ffma2(u64& d, u64 a, u64 b) {
    asm("fma.rn.f32x2 %0, %1, %2, %0;" : "+l"(d) : "l"(a), "l"(b));
}

// ---------------------------------------------------------------------------
// Kernel 1: Wh = h @ W   [8192,512] x [512,256], fp32 via packed f32x2 FMA
// block: 64x64 tile, 256 threads, micro-tile 4 rows x 4 cols (2 row-pairs)
// ---------------------------------------------------------------------------
__global__ __launch_bounds__(256) void k_gemm_wh(const float* __restrict__ h,
                                                 const float* __restrict__ W) {
    __shared__ __align__(16) float As[16][66];  // [k][m] transposed, stride 66 keeps u64 pairs 8B-aligned
    __shared__ __align__(16) float Bs[16][64];  // [k][n]
    const int bm = blockIdx.x * 64, bn = blockIdx.y * 64;
    const int tid = threadIdx.x;
    const int tx = tid & 15;    // col group: cols [4*tx, 4*tx+4)
    const int ty = tid >> 4;    // row group: rows [4*ty, 4*ty+4)

    u64 acc[2][4] = {};         // [row-pair][col] : pair = (2r, 2r+1) rows

    for (int k0 = 0; k0 < FIN; k0 += 16) {
        {   // A tile: 64 rows x 16 k, transposed into As[k][m]
            int m = tid >> 2, kq = tid & 3;
            float4 v = *(const float4*)&h[(size_t)(bm + m) * FIN + k0 + kq * 4];
            As[kq * 4 + 0][m] = v.x; As[kq * 4 + 1][m] = v.y;
            As[kq * 4 + 2][m] = v.z; As[kq * 4 + 3][m] = v.w;
        }
        {   // B tile: 16 k x 64 n
            int k = tid >> 4, n4 = tid & 15;
            *(float4*)&Bs[k][n4 * 4] = *(const float4*)&W[(size_t)(k0 + k) * FOUT + bn + n4 * 4];
        }
        __syncthreads();
        #pragma unroll
        for (int k = 0; k < 16; k++) {
            float4 b4 = *(const float4*)&Bs[k][tx * 4];
            u64 bx = pack2(b4.x, b4.x), by = pack2(b4.y, b4.y);
            u64 bz = pack2(b4.z, b4.z), bw = pack2(b4.w, b4.w);
            const u64* ap = (const u64*)&As[k][ty * 4];
            u64 a01 = ap[0], a23 = ap[1];
            ffma2(acc[0][0], a01, bx); ffma2(acc[0][1], a01, by);
            ffma2(acc[0][2], a01, bz); ffma2(acc[0][3], a01, bw);
            ffma2(acc[1][0], a23, bx); ffma2(acc[1][1], a23, by);
            ffma2(acc[1][2], a23, bz); ffma2(acc[1][3], a23, bw);
        }
        __syncthreads();
    }
    #pragma unroll
    for (int r = 0; r < 2; r++) {
        float e0, o0, e1, o1, e2, o2, e3, o3;
        unpack2(acc[r][0], e0, o0); unpack2(acc[r][1], e1, o1);
        unpack2(acc[r][2], e2, o2); unpack2(acc[r][3], e3, o3);
        float4 ve = make_float4(e0, e1, e2, e3);
        float4 vo = make_float4(o0, o1, o2, o3);
        *(float4*)&g_Wh[(size_t)(bm + ty * 4 + 2 * r + 0) * FOUT + bn + tx * 4] = ve;
        *(float4*)&g_Wh[(size_t)(bm + ty * 4 + 2 * r + 1) * FOUT + bn + tx * 4] = vo;
    }
}

// ---------------------------------------------------------------------------
// Kernel 2: f1_i = Wh_i . a[:256],  f2_i = Wh_i . a[256:]   (one warp per row)
// ---------------------------------------------------------------------------
__global__ __launch_bounds__(256) void k_f12(const float* __restrict__ a) {
    int warp = (blockIdx.x * blockDim.x + threadIdx.x) >> 5;
    int lane = threadIdx.x & 31;
    if (warp >= N_NODES) return;
    const float* wh = &g_Wh[(size_t)warp * FOUT];
    float s1 = 0.f, s2 = 0.f;
    #pragma unroll
    for (int k = 0; k < FOUT; k += 32) {
        float v = wh[k + lane];
        s1 += v * a[k + lane];
        s2 += v * a[FOUT + k + lane];
    }
    #pragma unroll
    for (int o = 16; o; o >>= 1) {
        s1 += __shfl_xor_sync(~0u, s1, o);
        s2 += __shfl_xor_sync(~0u, s2, o);
    }
    if (!lane) { g_f1[warp] = s1; g_f2[warp] = s2; }
}

// ---------------------------------------------------------------------------
// Kernel 3: gmax = max_j f2_j   (single block; deterministic tree reduce)
// ---------------------------------------------------------------------------
__global__ void k_gmax() {
    __shared__ float sm[256];
    float m = -1e30f;
    for (int i = threadIdx.x; i < N_NODES; i += 256) m = fmaxf(m, g_f2[i]);
    sm[threadIdx.x] = m;
    __syncthreads();
    for (int s = 128; s; s >>= 1) {
        if (threadIdx.x < s) sm[threadIdx.x] = fmaxf(sm[threadIdx.x], sm[threadIdx.x + s]);
        __syncthreads();
    }
    if (!threadIdx.x) g_gmax = sm[0];
}

// ---------------------------------------------------------------------------
// Kernel 4: fused masked-softmax-matmul + ELU.
//   Per block: 32 rows x all 8192 j (adj read once). Per thread: 8 rows x 4 cols.
//   p_ij = adj ? exp(leaky(f1_i+f2_j) - M_i) : 0,  with M_i = leaky(f1_i + gmax)
//   out_i = elu( (sum_j p_ij Wh_j) / (sum_j p_ij) )
//   Inner product done with packed f32x2 FMA (2 fp32 FMA / instr).
// ---------------------------------------------------------------------------
__global__ __launch_bounds__(256, 2) void k_attn(const int* __restrict__ adj,
                                                 float* __restrict__ out) {
    __shared__ __align__(16) float Whs[32][256];   // [j][f]   32 KB
    __shared__ __align__(16) float Ps[32][36];     // [j][i]   ~4.6 KB (stride 36 => 16B-aligned rows)
    __shared__ float Zrow[32];

    const int tid = threadIdx.x;
    const int i0 = blockIdx.x * 32;
    const int tx = tid & 63;      // col group: cols [4*tx, 4*tx+4)
    const int ty = tid >> 6;      // row group: rows [8*ty, 8*ty+8)
    // P-generation mapping: thread -> (row pr, 4 consecutive j at pc)
    const int pr = tid >> 3;
    const int pc = (tid & 7) * 4;

    const float f1r = g_f1[i0 + pr];
    const float gmax = g_gmax;
    const float Ms = f1r + gmax;
    const float M = Ms > 0.f ? Ms : ALPHA * Ms;   // per-row softmax shift (upper bound of row max)

    u64 acc[4][4] = {};    // [row-pair][col]; pair = rows (ty*8+2r, +1)
    float zreg = 0.f;      // row-sum of p, valid on lanes with (tid&7)==0

    for (int j0 = 0; j0 < N_NODES; j0 += 32) {
        __syncthreads();
        // ---- fill Whs: 32 x 256 floats, 8 float4 per thread, coalesced ----
        #pragma unroll
        for (int l = 0; l < 8; l++) {
            int lin = l * 256 + tid;           // float4 index (2048 total)
            int row = lin >> 6, c4 = lin & 63;
            *(float4*)&Whs[row][c4 * 4] =
                *(const float4*)&g_Wh[(size_t)(j0 + row) * FOUT + c4 * 4];
        }
        // ---- generate P tile (transposed: Ps[j][i]) + partial Z ----
        {
            const int4 av = *(const int4*)&adj[(size_t)(i0 + pr) * N_NODES + j0 + pc];
            const float4 f2v = *(const float4*)&g_f2[j0 + pc];
            const int aa[4] = {av.x, av.y, av.z, av.w};
            const float ff[4] = {f2v.x, f2v.y, f2v.z, f2v.w};
            float zp = 0.f;
            #pragma unroll
            for (int c = 0; c < 4; c++) {
                float s = f1r + ff[c];
                float e = s > 0.f ? s : ALPHA * s;
                float p = (aa[c] > 0) ? __expf(e - M) : 0.f;
                Ps[pc + c][pr] = p;
                zp += p;
            }
            // reduce the 8 threads that share row pr (lanes pr*8..pr*8+7)
            zp += __shfl_xor_sync(~0u, zp, 4);
            zp += __shfl_xor_sync(~0u, zp, 2);
            zp += __shfl_xor_sync(~0u, zp, 1);
            zreg += zp;
        }
        __syncthreads();
        // ---- rank-32 update: acc += P[:, jj] * Wh[jj, :] ----
        #pragma unroll
        for (int jj = 0; jj < 32; jj++) {
            const u64* pp = (const u64*)&Ps[jj][ty * 8];   // row pairs, broadcast in warp
            u64 p01 = pp[0], p23 = pp[1], p45 = pp[2], p67 = pp[3];
            float4 w4 = *(const float4*)&Whs[jj][tx * 4];  // conflict-free 512B sweep
            u64 wx = pack2(w4.x, w4.x), wy = pack2(w4.y, w4.y);
            u64 wz = pack2(w4.z, w4.z), ww = pack2(w4.w, w4.w);
            ffma2(acc[0][0], p01, wx); ffma2(acc[0][1], p01, wy);
            ffma2(acc[0][2], p01, wz); ffma2(acc[0][3], p01, ww);
            ffma2(acc[1][0], p23, wx); ffma2(acc[1][1], p23, wy);
            ffma2(acc[1][2], p23, wz); ffma2(acc[1][3], p23, ww);
            ffma2(acc[2][0], p45, wx); ffma2(acc[2][1], p45, wy);
            ffma2(acc[2][2], p45, wz); ffma2(acc[2][3], p45, ww);
            ffma2(acc[3][0], p67, wx); ffma2(acc[3][1], p67, wy);
            ffma2(acc[3][2], p67, wz); ffma2(acc[3][3], p67, ww);
        }
    }

    if ((tid & 7) == 0) Zrow[pr] = zreg;
    __syncthreads();

    // ---- normalize + ELU + store ----
    #pragma unroll
    for (int r = 0; r < 4; r++) {
        int row_e = ty * 8 + 2 * r;
        float invZe = 1.f / Zrow[row_e];
        float invZo = 1.f / Zrow[row_e + 1];
        float e0, o0, e1, o1, e2, o2, e3, o3;
        unpack2(acc[r][0], e0, o0); unpack2(acc[r][1], e1, o1);
        unpack2(acc[r][2], e2, o2); unpack2(acc[r][3], e3, o3);
        float4 ve, vo;
        e0 *= invZe; e1 *= invZe; e2 *= invZe; e3 *= invZe;
        o0 *= invZo; o1 *= invZo; o2 *= invZo; o3 *= invZo;
        ve.x = e0 > 0.f ? e0 : expm1f(e0);
        ve.y = e1 > 0.f ? e1 : expm1f(e1);
        ve.z = e2 > 0.f ? e2 : expm1f(e2);
        ve.w = e3 > 0.f ? e3 : expm1f(e3);
        vo.x = o0 > 0.f ? o0 : expm1f(o0);
        vo.y = o1 > 0.f ? o1 : expm1f(o1);
        vo.z = o2 > 0.f ? o2 : expm1f(o2);
        vo.w = o3 > 0.f ? o3 : expm1f(o3);
        *(float4*)&out[(size_t)(i0 + row_e + 0) * FOUT + tx * 4] = ve;
        *(float4*)&out[(size_t)(i0 + row_e + 1) * FOUT + tx * 4] = vo;
    }
}

// ---------------------------------------------------------------------------
extern "C" void kernel_launch(void* const* d_in, const int* in_sizes, int n_in,
                              void* d_out, int out_size) {
    const float* h   = (const float*)d_in[0];
    const int*   adj = (const int*)d_in[1];
    const float* W   = (const float*)d_in[2];
    const float* a   = (const float*)d_in[3];
    float* out = (float*)d_out;

    dim3 g1(N_NODES / 64, FOUT / 64);
    k_gemm_wh<<<g1, 256>>>(h, W);
    k_f12<<<N_NODES / 8, 256>>>(a);        // 8 rows (warps) per block
    k_gmax<<<1, 256>>>();
    k_attn<<<N_NODES / 32, 256>>>(adj, out);
}

// round 3
// speedup vs baseline: 3.2819x; 3.2819x over previous
#include <cuda_runtime.h>
#include <cuda_bf16.h>
#include <cstdint>

#define N_NODES 8192
#define FIN 512
#define FOUT 256
#define ALPHA 0.2f

// Tensor-core path is only valid when the device target is sm_103a-specific.
#if defined(__CUDA_ARCH__) && defined(__CUDA_ARCH_FEAT_SM103_ALL)
#define TC_ON 1
#else
#define TC_ON 0
#endif

#define SPLITS 2
#define JSPAN (N_NODES / SPLITS)
#define KC 64
#define STAGES (JSPAN / KC)
#define TM 128

// ---- scratch (no cudaMalloc allowed) ----
__device__ float g_Wh[N_NODES * FOUT];                  // 8 MB
__device__ float g_f1[N_NODES];
__device__ float g_f2[N_NODES];
__device__ float g_gmax;
__device__ __nv_bfloat16 g_WhT_hi[FOUT * N_NODES];      // 4 MB (tc path)
__device__ __nv_bfloat16 g_WhT_lo[FOUT * N_NODES];      // 4 MB (tc path)
__device__ float g_Up[2LL * N_NODES * FOUT];            // 16 MB (tc path)
__device__ float g_Zp[2 * N_NODES];                     // (tc path)

typedef unsigned long long u64;

// ---------------- fp32x2 helpers ----------------
__device__ __forceinline__ u64 pack2(float lo, float hi) {
    u64 r; asm("mov.b64 %0, {%1, %2};" : "=l"(r) : "f"(lo), "f"(hi)); return r;
}
__device__ __forceinline__ void unpack2(u64 v, float& lo, float& hi) {
    asm("mov.b64 {%0, %1}, %2;" : "=f"(lo), "=f"(hi) : "l"(v));
}
__device__ __forceinline__ void ffma2(u64& d, u64 a, u64 b) {
    asm("fma.rn.f32x2 %0, %1, %2, %0;" : "+l"(d) : "l"(a), "l"(b));
}
__device__ __forceinline__ uint32_t smem_u32(const void* p) {
    uint32_t a;
    asm("{ .reg .u64 t; cvta.to.shared.u64 t, %1; cvt.u32.u64 %0, t; }" : "=r"(a) : "l"(p));
    return a;
}
__device__ __forceinline__ uint32_t bf16x2_pack(float lo, float hi) {
    uint32_t r; asm("cvt.rn.bf16x2.f32 %0, %1, %2;" : "=r"(r) : "f"(hi), "f"(lo)); return r;
}
__device__ __forceinline__ uint32_t swz(uint32_t off) { return off ^ ((off >> 3) & 0x70); }

#define CP16(dst, src)    asm volatile("cp.async.cg.shared.global [%0], [%1], 16;" :: "r"(dst), "l"(src) : "memory")
#define CP_COMMIT()       asm volatile("cp.async.commit_group;" ::: "memory")
#define CP_WAIT0()        asm volatile("cp.async.wait_group 0;" ::: "memory")

// ---------------------------------------------------------------------------
// Kernel 1: Wh = h @ W  (fp32, packed f32x2 FMA)
// ---------------------------------------------------------------------------
__global__ __launch_bounds__(256) void k_gemm_wh(const float* __restrict__ h,
                                                 const float* __restrict__ W) {
    __shared__ __align__(16) float As[16][66];
    __shared__ __align__(16) float Bs[16][64];
    const int bm = blockIdx.x * 64, bn = blockIdx.y * 64;
    const int tid = threadIdx.x;
    const int tx = tid & 15, ty = tid >> 4;
    u64 acc[2][4] = {};
    for (int k0 = 0; k0 < FIN; k0 += 16) {
        {
            int m = tid >> 2, kq = tid & 3;
            float4 v = *(const float4*)&h[(size_t)(bm + m) * FIN + k0 + kq * 4];
            As[kq * 4 + 0][m] = v.x; As[kq * 4 + 1][m] = v.y;
            As[kq * 4 + 2][m] = v.z; As[kq * 4 + 3][m] = v.w;
        }
        {
            int k = tid >> 4, n4 = tid & 15;
            *(float4*)&Bs[k][n4 * 4] = *(const float4*)&W[(size_t)(k0 + k) * FOUT + bn + n4 * 4];
        }
        __syncthreads();
        #pragma unroll
        for (int k = 0; k < 16; k++) {
            float4 b4 = *(const float4*)&Bs[k][tx * 4];
            u64 bx = pack2(b4.x, b4.x), by = pack2(b4.y, b4.y);
            u64 bz = pack2(b4.z, b4.z), bw = pack2(b4.w, b4.w);
            const u64* ap = (const u64*)&As[k][ty * 4];
            u64 a01 = ap[0], a23 = ap[1];
            ffma2(acc[0][0], a01, bx); ffma2(acc[0][1], a01, by);
            ffma2(acc[0][2], a01, bz); ffma2(acc[0][3], a01, bw);
            ffma2(acc[1][0], a23, bx); ffma2(acc[1][1], a23, by);
            ffma2(acc[1][2], a23, bz); ffma2(acc[1][3], a23, bw);
        }
        __syncthreads();
    }
    #pragma unroll
    for (int r = 0; r < 2; r++) {
        float e0, o0, e1, o1, e2, o2, e3, o3;
        unpack2(acc[r][0], e0, o0); unpack2(acc[r][1], e1, o1);
        unpack2(acc[r][2], e2, o2); unpack2(acc[r][3], e3, o3);
        *(float4*)&g_Wh[(size_t)(bm + ty * 4 + 2 * r + 0) * FOUT + bn + tx * 4] = make_float4(e0, e1, e2, e3);
        *(float4*)&g_Wh[(size_t)(bm + ty * 4 + 2 * r + 1) * FOUT + bn + tx * 4] = make_float4(o0, o1, o2, o3);
    }
}

// ---------------------------------------------------------------------------
// Kernel 2: f1/f2 row dots; Kernel 3: gmax
// ---------------------------------------------------------------------------
__global__ __launch_bounds__(256) void k_f12(const float* __restrict__ a) {
    int warp = (blockIdx.x * blockDim.x + threadIdx.x) >> 5;
    int lane = threadIdx.x & 31;
    if (warp >= N_NODES) return;
    const float* wh = &g_Wh[(size_t)warp * FOUT];
    float s1 = 0.f, s2 = 0.f;
    #pragma unroll
    for (int k = 0; k < FOUT; k += 32) {
        float v = wh[k + lane];
        s1 += v * a[k + lane];
        s2 += v * a[FOUT + k + lane];
    }
    #pragma unroll
    for (int o = 16; o; o >>= 1) {
        s1 += __shfl_xor_sync(~0u, s1, o);
        s2 += __shfl_xor_sync(~0u, s2, o);
    }
    if (!lane) { g_f1[warp] = s1; g_f2[warp] = s2; }
}
__global__ void k_gmax() {
    __shared__ float sm[256];
    float m = -1e30f;
    for (int i = threadIdx.x; i < N_NODES; i += 256) m = fmaxf(m, g_f2[i]);
    sm[threadIdx.x] = m; __syncthreads();
    for (int s = 128; s; s >>= 1) {
        if (threadIdx.x < s) sm[threadIdx.x] = fmaxf(sm[threadIdx.x], sm[threadIdx.x + s]);
        __syncthreads();
    }
    if (!threadIdx.x) g_gmax = sm[0];
}

// ===========================================================================
// ===================== TENSOR-CORE PATH (sm_103a only) =====================
// ===========================================================================
#define TC_SMEM 213248
#define AHI_OFF 0
#define ALO_OFF 32768
#define BHI_OFF 65536
#define BLO_OFF 131072
#define F2_OFF  196608
#define MB_OFF  212992

#if TC_ON
static constexpr uint64_t DESC_BASE_SW128 =
    (uint64_t(2) << 61) | (uint64_t(1) << 46) | (uint64_t(64) << 32) | (uint64_t(1) << 16);
__device__ __forceinline__ uint64_t mk_desc(uint32_t addr) {
    return DESC_BASE_SW128 | ((uint64_t)(addr >> 4) & 0x3FFF);
}
__device__ __forceinline__ void mma_f16_ss(uint32_t d, uint64_t ad, uint64_t bd,
                                           uint32_t idesc, uint32_t en) {
    asm volatile(
        "{\n\t.reg .pred p;\n\t"
        "setp.ne.u32 p, %5, 0;\n\t"
        "tcgen05.mma.cta_group::1.kind::f16 [%0], %1, %2, %3, {%4, %4, %4, %4}, p;\n\t}"
        :: "r"(d), "l"(ad), "l"(bd), "r"(idesc), "r"(0u), "r"(en) : "memory");
}
#define TC_ALLOC(sa, n)   asm volatile("tcgen05.alloc.cta_group::1.sync.aligned.shared::cta.b32 [%0], %1;" :: "r"(sa), "r"(n) : "memory")
#define TC_DEALLOC(t, n)  asm volatile("tcgen05.dealloc.cta_group::1.sync.aligned.b32 %0, %1;" :: "r"(t), "r"(n))
#define TC_RELINQ()       asm volatile("tcgen05.relinquish_alloc_permit.cta_group::1.sync.aligned;")
#define TC_COMMIT(mb)     asm volatile("tcgen05.commit.cta_group::1.mbarrier::arrive::one.shared::cluster.b64 [%0];" :: "r"(mb) : "memory")
#define TC_WAIT_LD()      asm volatile("tcgen05.wait::ld.sync.aligned;" ::: "memory")
#define TC_FENCE_AFTER()  asm volatile("tcgen05.fence::after_thread_sync;" ::: "memory")
#define FENCE_PROXY()     asm volatile("fence.proxy.async;" ::: "memory")
#define MBAR_INIT(mb, n)  asm volatile("mbarrier.init.shared.b64 [%0], %1;" :: "r"(mb), "r"(n) : "memory")
#define MBAR_WAIT(mb, ph) do {                                                            \
    uint32_t _m = (mb), _p = (ph), _d;                                                    \
    asm volatile("{\n\t.reg .pred p;\n\t"                                                 \
        "mbarrier.try_wait.parity.acquire.cta.shared::cta.b64 p, [%1], %2;\n\t"           \
        "selp.b32 %0, 1, 0, p;\n\t}" : "=r"(_d) : "r"(_m), "r"(_p) : "memory");           \
    if (!_d) {                                                                            \
        asm volatile("{\n\t.reg .pred P1;\n\t"                                            \
            "W%=:\n\t"                                                                    \
            "mbarrier.try_wait.parity.acquire.cta.shared::cta.b64 P1, [%0], %1, 0x989680;\n\t" \
            "@P1 bra.uni D%=;\n\t"                                                        \
            "bra.uni W%=;\n\t"                                                            \
            "D%=:\n\t}" :: "r"(_m), "r"(_p) : "memory");                                  \
    }                                                                                     \
} while (0)
#define STS128A(a, r0, r1, r2, r3) asm volatile("st.shared.v4.b32 [%0], {%1,%2,%3,%4};" :: "r"(a), "r"(r0), "r"(r1), "r"(r2), "r"(r3) : "memory")
#define LDTM_X32(r, t) \
    asm volatile("tcgen05.ld.sync.aligned.32x32b.x32.b32 " \
        "{%0,%1,%2,%3,%4,%5,%6,%7,%8,%9,%10,%11,%12,%13,%14,%15," \
        "%16,%17,%18,%19,%20,%21,%22,%23,%24,%25,%26,%27,%28,%29,%30,%31}, [%32];" \
        : "=r"((r)[0]),"=r"((r)[1]),"=r"((r)[2]),"=r"((r)[3]),"=r"((r)[4]),"=r"((r)[5]),"=r"((r)[6]),"=r"((r)[7]), \
          "=r"((r)[8]),"=r"((r)[9]),"=r"((r)[10]),"=r"((r)[11]),"=r"((r)[12]),"=r"((r)[13]),"=r"((r)[14]),"=r"((r)[15]), \
          "=r"((r)[16]),"=r"((r)[17]),"=r"((r)[18]),"=r"((r)[19]),"=r"((r)[20]),"=r"((r)[21]),"=r"((r)[22]),"=r"((r)[23]), \
          "=r"((r)[24]),"=r"((r)[25]),"=r"((r)[26]),"=r"((r)[27]),"=r"((r)[28]),"=r"((r)[29]),"=r"((r)[30]),"=r"((r)[31]) \
        : "r"(t))

static constexpr uint32_t IDESC =
    (1u << 4) | (1u << 7) | (1u << 10) | ((FOUT / 8) << 17) | ((TM / 16) << 24);

__global__ __launch_bounds__(256) void k_split() {
    __shared__ float S[64][65];
    const int j0 = blockIdx.x * 64, f0 = blockIdx.y * 64;
    const int t = threadIdx.x;
    #pragma unroll
    for (int r = 0; r < 4; r++) {
        int jl = r * 16 + (t >> 4);
        float4 v = *(const float4*)&g_Wh[(size_t)(j0 + jl) * FOUT + f0 + (t & 15) * 4];
        S[jl][(t & 15) * 4 + 0] = v.x; S[jl][(t & 15) * 4 + 1] = v.y;
        S[jl][(t & 15) * 4 + 2] = v.z; S[jl][(t & 15) * 4 + 3] = v.w;
    }
    __syncthreads();
    const int fl = t >> 2, jq = (t & 3) * 16;
    uint32_t hw[8], lw[8];
    #pragma unroll
    for (int c = 0; c < 8; c++) {
        float w0 = S[jq + 2 * c][fl], w1 = S[jq + 2 * c + 1][fl];
        uint32_t h = bf16x2_pack(w0, w1);
        float he = __uint_as_float(h << 16);
        float ho = __uint_as_float(h & 0xFFFF0000u);
        hw[c] = h;
        lw[c] = bf16x2_pack(w0 - he, w1 - ho);
    }
    size_t base = (size_t)(f0 + fl) * N_NODES + j0 + jq;
    *(uint4*)&g_WhT_hi[base]     = make_uint4(hw[0], hw[1], hw[2], hw[3]);
    *(uint4*)&g_WhT_hi[base + 8] = make_uint4(hw[4], hw[5], hw[6], hw[7]);
    *(uint4*)&g_WhT_lo[base]     = make_uint4(lw[0], lw[1], lw[2], lw[3]);
    *(uint4*)&g_WhT_lo[base + 8] = make_uint4(lw[4], lw[5], lw[6], lw[7]);
}

__global__ __launch_bounds__(256, 1) void k_attn_tc(const int* __restrict__ adj) {
    extern __shared__ __align__(1024) char smem_raw[];
    const uint32_t sb = smem_u32(smem_raw);
    const int tid = threadIdx.x;
    const int wid = tid >> 5;
    const int split = blockIdx.x & 1;
    const int i0 = (blockIdx.x >> 1) * TM;
    const int jbase = split * JSPAN;

    if (wid == 0) TC_ALLOC(sb + MB_OFF + 16, 256);
    if (tid == 0) { MBAR_INIT(sb + MB_OFF + 0, 1); MBAR_INIT(sb + MB_OFF + 8, 1); }
    float* f2s = (float*)(smem_raw + F2_OFF);
    #pragma unroll
    for (int q = 0; q < 4; q++)
        *(float4*)&f2s[(q * 256 + tid) * 4] = *(const float4*)&g_f2[jbase + (q * 256 + tid) * 4];
    __syncthreads();
    const uint32_t tmem = *(const uint32_t*)(smem_raw + MB_OFF + 16);

    const int pr = tid >> 1, half = tid & 1;
    const float f1r = g_f1[i0 + pr];
    const float gm = g_gmax;
    const float Ms = f1r + gm;
    const float M = fmaxf(Ms, ALPHA * Ms);
    const long arow = (long)(i0 + pr) * N_NODES + jbase + half * 32;
    float zreg = 0.f;

    for (int s = 0; s < STAGES; s++) {
        const int buf = s & 1;
        const int round = s >> 1;
        if (s >= 2) { MBAR_WAIT(sb + MB_OFF + buf * 8, (round - 1) & 1); }
        {
            const size_t jcol = (size_t)jbase + s * KC;
            const uint32_t bh = sb + BHI_OFF + buf * 32768;
            const uint32_t bl = sb + BLO_OFF + buf * 32768;
            #pragma unroll
            for (int q = 0; q < 8; q++) {
                int m = q * 256 + tid;
                int f = m >> 3, k16 = m & 7;
                uint32_t d = swz((uint32_t)(f * 128 + k16 * 16));
                CP16(bh + d, (const char*)&g_WhT_hi[(size_t)f * N_NODES + jcol + k16 * 8]);
                CP16(bl + d, (const char*)&g_WhT_lo[(size_t)f * N_NODES + jcol + k16 * 8]);
            }
            CP_COMMIT();
        }
        {
            const int4* aptr = (const int4*)(adj + arow + s * KC);
            const uint32_t ah = sb + AHI_OFF + buf * 16384;
            const uint32_t al = sb + ALO_OFF + buf * 16384;
            const float* fp = &f2s[s * KC + half * 32];
            #pragma unroll
            for (int g = 0; g < 4; g++) {
                int4 a0 = aptr[2 * g], a1 = aptr[2 * g + 1];
                float4 f20 = *(const float4*)&fp[g * 8];
                float4 f21 = *(const float4*)&fp[g * 8 + 4];
                float p[8];
                {
                    const int am[8] = {a0.x, a0.y, a0.z, a0.w, a1.x, a1.y, a1.z, a1.w};
                    const float fv[8] = {f20.x, f20.y, f20.z, f20.w, f21.x, f21.y, f21.z, f21.w};
                    #pragma unroll
                    for (int c = 0; c < 8; c++) {
                        float e = f1r + fv[c];
                        e = fmaxf(e, ALPHA * e);
                        float pv = __expf(e - M);
                        p[c] = (am[c] > 0) ? pv : 0.f;
                        zreg += p[c];
                    }
                }
                uint32_t hw[4], lw[4];
                #pragma unroll
                for (int c = 0; c < 4; c++) {
                    uint32_t h = bf16x2_pack(p[2 * c], p[2 * c + 1]);
                    float he = __uint_as_float(h << 16);
                    float ho = __uint_as_float(h & 0xFFFF0000u);
                    hw[c] = h;
                    lw[c] = bf16x2_pack(p[2 * c] - he, p[2 * c + 1] - ho);
                }
                uint32_t so = swz((uint32_t)(pr * 128 + half * 64 + g * 16));
                STS128A(ah + so, hw[0], hw[1], hw[2], hw[3]);
                STS128A(al + so, lw[0], lw[1], lw[2], lw[3]);
            }
        }
        CP_WAIT0();
        __syncthreads();
        if (tid == 0) {
            FENCE_PROXY();
            uint64_t ah = mk_desc(sb + AHI_OFF + buf * 16384);
            uint64_t al = mk_desc(sb + ALO_OFF + buf * 16384);
            uint64_t bh = mk_desc(sb + BHI_OFF + buf * 32768);
            uint64_t bl = mk_desc(sb + BLO_OFF + buf * 32768);
            const uint64_t pa[3] = {ah, ah, al};
            const uint64_t pb[3] = {bh, bl, bh};
            #pragma unroll
            for (int pass = 0; pass < 3; pass++)
                #pragma unroll
                for (int k = 0; k < 4; k++) {
                    uint32_t en = !(s == 0 && pass == 0 && k == 0);
                    mma_f16_ss(tmem, pa[pass] + k * 2, pb[pass] + k * 2, IDESC, en);
                }
            TC_COMMIT(sb + MB_OFF + buf * 8);
        }
    }

    zreg += __shfl_xor_sync(~0u, zreg, 1);
    if (!half) g_Zp[split * N_NODES + i0 + pr] = zreg;

    MBAR_WAIT(sb + MB_OFF + ((STAGES - 1) & 1) * 8, ((STAGES - 1) >> 1) & 1);
    TC_FENCE_AFTER();
    if (wid < 4) {
        const int lane = tid & 31;
        float* up = &g_Up[(size_t)split * N_NODES * FOUT + (size_t)(i0 + wid * 32 + lane) * FOUT];
        #pragma unroll
        for (int cb = 0; cb < FOUT; cb += 32) {
            uint32_t r[32];
            LDTM_X32(r, tmem + cb);
            TC_WAIT_LD();
            #pragma unroll
            for (int c = 0; c < 32; c += 4)
                *(float4*)&up[cb + c] = make_float4(
                    __uint_as_float(r[c]), __uint_as_float(r[c + 1]),
                    __uint_as_float(r[c + 2]), __uint_as_float(r[c + 3]));
        }
    }
    __syncthreads();
    if (wid == 0) { TC_RELINQ(); TC_DEALLOC(tmem, 256); }
}

__global__ __launch_bounds__(256) void k_final(float* __restrict__ out) {
    const int row = blockIdx.x, c = threadIdx.x;
    float z = g_Zp[row] + g_Zp[N_NODES + row];
    float u = g_Up[(size_t)row * FOUT + c] +
              g_Up[(size_t)N_NODES * FOUT + (size_t)row * FOUT + c];
    float v = u / z;
    out[(size_t)row * FOUT + c] = v > 0.f ? v : expm1f(v);
}

// fallback kernel is a stub in tc mode
__global__ __launch_bounds__(256, 2) void k_attn_fb(const int* __restrict__ adj,
                                                    float* __restrict__ out) {}

#else  // ================== CUDA-CORE FALLBACK PATH ==========================

// stubs for tc-mode kernels
__global__ __launch_bounds__(256) void k_split() {}
__global__ __launch_bounds__(256, 1) void k_attn_tc(const int* __restrict__ adj) {}
__global__ __launch_bounds__(256) void k_final(float* __restrict__ out) {}

// ---------------------------------------------------------------------------
// Fallback attention: fused masked-softmax-matmul + ELU with f32x2 FMA.
// 32 rows/CTA, 32-j tiles, double-buffered cp.async Whs + reg-prefetched
// adj/f2, P computed for next tile after the FFMA block. ONE barrier/tile.
// Dynamic smem: Whs 2x32x256 f32 (65536B) + Ps 2x32x36 (9216B) + Zrow (128B)
// ---------------------------------------------------------------------------
#define FB_WHS(buf) ((buf) * 8192)
#define FB_PS(buf)  (16384 + (buf) * 1152)
#define FB_ZR       18688

__global__ __launch_bounds__(256, 2) void k_attn_fb(const int* __restrict__ adj,
                                                    float* __restrict__ out) {
    extern __shared__ __align__(16) float fsm[];
    const uint32_t sb = smem_u32(fsm);
    const int tid = threadIdx.x;
    const int i0 = blockIdx.x * 32;
    const int tx = tid & 63;      // FFMA cols [4*tx, 4*tx+4)
    const int ty = tid >> 6;      // FFMA rows [8*ty, 8*ty+8)
    const int pr = tid >> 3;      // P row
    const int pc = (tid & 7) * 4; // P cols (4 j)

    const float f1r = g_f1[i0 + pr];
    const float gm = g_gmax;
    const float Ms = f1r + gm;
    const float M = fmaxf(Ms, ALPHA * Ms);
    const size_t arowbase = (size_t)(i0 + pr) * N_NODES;

    u64 acc[4][4] = {};
    float zreg = 0.f;

    // ---- prologue: fill tile 0 ----
    {
        #pragma unroll
        for (int l = 0; l < 8; l++) {
            int lin = l * 256 + tid;
            int row = lin >> 6, c4 = lin & 63;
            CP16(sb + (uint32_t)(FB_WHS(0) + row * 256 + c4 * 4) * 4,
                 (const char*)&g_Wh[(size_t)row * FOUT + c4 * 4]);
        }
        CP_COMMIT();
        int4 av = *(const int4*)(adj + arowbase + pc);
        float4 fv = *(const float4*)&g_f2[pc];
        const int am[4] = {av.x, av.y, av.z, av.w};
        const float ff[4] = {fv.x, fv.y, fv.z, fv.w};
        #pragma unroll
        for (int c = 0; c < 4; c++) {
            float e = f1r + ff[c];
            e = fmaxf(e, ALPHA * e);
            float p = (am[c] > 0) ? __expf(e - M) : 0.f;
            zreg += p;
            fsm[FB_PS(0) + (pc + c) * 36 + pr] = p;
        }
        CP_WAIT0();
        __syncthreads();
    }

    for (int s = 0; s < 256; s++) {
        const int cur = s & 1;
        int4 a_pf; float4 f2_pf;
        const bool more = (s < 255);
        if (more) {
            const int j0n = (s + 1) * 32;
            #pragma unroll
            for (int l = 0; l < 8; l++) {
                int lin = l * 256 + tid;
                int row = lin >> 6, c4 = lin & 63;
                CP16(sb + (uint32_t)(FB_WHS(cur ^ 1) + row * 256 + c4 * 4) * 4,
                     (const char*)&g_Wh[(size_t)(j0n + row) * FOUT + c4 * 4]);
            }
            CP_COMMIT();
            a_pf = *(const int4*)(adj + arowbase + j0n + pc);
            f2_pf = *(const float4*)&g_f2[j0n + pc];
        }

        // ---- rank-32 FFMA2 update over buffer `cur` ----
        const float* Whc = &fsm[FB_WHS(cur)];
        const float* Psc = &fsm[FB_PS(cur)];
        #pragma unroll
        for (int jj = 0; jj < 32; jj++) {
            const u64* pp = (const u64*)&Psc[jj * 36 + ty * 8];
            u64 p01 = pp[0], p23 = pp[1], p45 = pp[2], p67 = pp[3];
            float4 w4 = *(const float4*)&Whc[jj * 256 + tx * 4];
            u64 wx = pack2(w4.x, w4.x), wy = pack2(w4.y, w4.y);
            u64 wz = pack2(w4.z, w4.z), ww = pack2(w4.w, w4.w);
            ffma2(acc[0][0], p01, wx); ffma2(acc[0][1], p01, wy);
            ffma2(acc[0][2], p01, wz); ffma2(acc[0][3], p01, ww);
            ffma2(acc[1][0], p23, wx); ffma2(acc[1][1], p23, wy);
            ffma2(acc[1][2], p23, wz); ffma2(acc[1][3], p23, ww);
            ffma2(acc[2][0], p45, wx); ffma2(acc[2][1], p45, wy);
            ffma2(acc[2][2], p45, wz); ffma2(acc[2][3], p45, ww);
            ffma2(acc[3][0], p67, wx); ffma2(acc[3][1], p67, wy);
            ffma2(acc[3][2], p67, wz); ffma2(acc[3][3], p67, ww);
        }

        if (more) {
            const int am[4] = {a_pf.x, a_pf.y, a_pf.z, a_pf.w};
            const float ff[4] = {f2_pf.x, f2_pf.y, f2_pf.z, f2_pf.w};
            #pragma unroll
            for (int c = 0; c < 4; c++) {
                float e = f1r + ff[c];
                e = fmaxf(e, ALPHA * e);
                float p = (am[c] > 0) ? __expf(e - M) : 0.f;
                zreg += p;
                fsm[FB_PS(cur ^ 1) + (pc + c) * 36 + pr] = p;
            }
            CP_WAIT0();
        }
        __syncthreads();
    }

    // ---- Z reduce (8 threads per row, consecutive lanes) ----
    zreg += __shfl_xor_sync(~0u, zreg, 4);
    zreg += __shfl_xor_sync(~0u, zreg, 2);
    zreg += __shfl_xor_sync(~0u, zreg, 1);
    if ((tid & 7) == 0) fsm[FB_ZR + pr] = zreg;
    __syncthreads();

    // ---- normalize + ELU + store ----
    #pragma unroll
    for (int r = 0; r < 4; r++) {
        int row_e = ty * 8 + 2 * r;
        float invZe = 1.f / fsm[FB_ZR + row_e];
        float invZo = 1.f / fsm[FB_ZR + row_e + 1];
        float e0, o0, e1, o1, e2, o2, e3, o3;
        unpack2(acc[r][0], e0, o0); unpack2(acc[r][1], e1, o1);
        unpack2(acc[r][2], e2, o2); unpack2(acc[r][3], e3, o3);
        e0 *= invZe; e1 *= invZe; e2 *= invZe; e3 *= invZe;
        o0 *= invZo; o1 *= invZo; o2 *= invZo; o3 *= invZo;
        float4 ve, vo;
        ve.x = e0 > 0.f ? e0 : expm1f(e0);
        ve.y = e1 > 0.f ? e1 : expm1f(e1);
        ve.z = e2 > 0.f ? e2 : expm1f(e2);
        ve.w = e3 > 0.f ? e3 : expm1f(e3);
        vo.x = o0 > 0.f ? o0 : expm1f(o0);
        vo.y = o1 > 0.f ? o1 : expm1f(o1);
        vo.z = o2 > 0.f ? o2 : expm1f(o2);
        vo.w = o3 > 0.f ? o3 : expm1f(o3);
        *(float4*)&out[(size_t)(i0 + row_e + 0) * FOUT + tx * 4] = ve;
        *(float4*)&out[(size_t)(i0 + row_e + 1) * FOUT + tx * 4] = vo;
    }
}
#endif  // TC_ON

#define FB_SMEM 74880

// ---------------------------------------------------------------------------
extern "C" void kernel_launch(void* const* d_in, const int* in_sizes, int n_in,
                              void* d_out, int out_size) {
    const float* h   = (const float*)d_in[0];
    const int*   adj = (const int*)d_in[1];
    const float* W   = (const float*)d_in[2];
    const float* a   = (const float*)d_in[3];
    float* out = (float*)d_out;

    cudaFuncSetAttribute(k_attn_tc, cudaFuncAttributeMaxDynamicSharedMemorySize, TC_SMEM);
    cudaFuncSetAttribute(k_attn_fb, cudaFuncAttributeMaxDynamicSharedMemorySize, FB_SMEM);

    dim3 g1(N_NODES / 64, FOUT / 64);
    k_gemm_wh<<<g1, 256>>>(h, W);
    k_split<<<dim3(N_NODES / 64, FOUT / 64), 256>>>();          // stub in fb mode
    k_f12<<<N_NODES / 8, 256>>>(a);
    k_gmax<<<1, 256>>>();
    k_attn_tc<<<N_NODES / TM * SPLITS, 256, TC_SMEM>>>(adj);    // stub in fb mode
    k_attn_fb<<<N_NODES / 32, 256, FB_SMEM>>>(adj, out);        // stub in tc mode
    k_final<<<N_NODES, 256>>>(out);                             // stub in fb mode
}